// round 2
// baseline (speedup 1.0000x reference)
#include <cuda_runtime.h>
#include <cstdint>

// ============================================================================
// Bit-exact JAX threefry2x32 (partitionable semantics, confirmed by R1 error
// signature: masks/positions matched, only randint value draws were off).
// ============================================================================

#define TF_ROUND(x0, x1, r) { x0 += x1; x1 = __funnelshift_l(x1, x1, (r)); x1 ^= x0; }

#define TF_R4A(x0, x1) { TF_ROUND(x0,x1,13) TF_ROUND(x0,x1,15) TF_ROUND(x0,x1,26) TF_ROUND(x0,x1,6) }
#define TF_R4B(x0, x1) { TF_ROUND(x0,x1,17) TF_ROUND(x0,x1,29) TF_ROUND(x0,x1,16) TF_ROUND(x0,x1,24) }

struct TKey { uint32_t a, b, c; };

__device__ __forceinline__ TKey mk_key(uint32_t k0, uint32_t k1) {
    TKey k; k.a = k0; k.b = k1; k.c = k0 ^ k1 ^ 0x1BD11BDAu; return k;
}

__device__ __forceinline__ void tf_pair(const TKey k, uint32_t c0, uint32_t c1,
                                        uint32_t& o0, uint32_t& o1) {
    uint32_t x0 = c0 + k.a, x1 = c1 + k.b;
    TF_R4A(x0, x1); x0 += k.b; x1 += k.c + 1u;
    TF_R4B(x0, x1); x0 += k.c; x1 += k.a + 2u;
    TF_R4A(x0, x1); x0 += k.a; x1 += k.b + 3u;
    TF_R4B(x0, x1); x0 += k.b; x1 += k.c + 4u;
    TF_R4A(x0, x1); x0 += k.c; x1 += k.a + 5u;
    o0 = x0; o1 = x1;
}

// Partitionable 32-bit random bits at 64-bit counter (0, idx): out0 ^ out1.
__device__ __forceinline__ uint32_t tf_bits(const TKey k, uint32_t idx) {
    uint32_t o0, o1;
    tf_pair(k, 0u, idx, o0, o1);
    return o0 ^ o1;
}

// uniform(bits) < e  <=>  (bits >> 9) < ceil(e * 2^23)   (exact: u = m / 2^23)
__device__ __forceinline__ uint32_t thresh_of(float e) {
    return (uint32_t)ceil((double)e * 8388608.0);   // constant-folded
}

// ============================================================================
// Fused channel kernel: one thread per (row b, channel c).
// sub -> del(compaction) -> ins(expansion) in one sequential pass.
// ============================================================================

__global__ void __launch_bounds__(128)
channel_m_kernel(const float* __restrict__ x, float* __restrict__ out, int B) {
    const int t = blockIdx.x * blockDim.x + threadIdx.x;
    if (t >= B * 4) return;

    const int c = t & 3;      // channel
    const int b = t >> 2;     // row
    const int L = 512;
    const int Lp = 514;       // L + 2

    const uint32_t Ksub = thresh_of(0.02f);
    const uint32_t Kdel = thresh_of(0.01f);
    const uint32_t Kins = thresh_of(0.01f);

    // ---- key derivation (foldlike split: key_i = tf(key, (0, i)))
    uint32_t t0, t1;
    const TKey root = mk_key(0u, 42u);                 // jax.random.key(42)
    tf_pair(root, 0u, (uint32_t)c, t0, t1);            // fold_in(key, c)
    const TKey kc = mk_key(t0, t1);

    tf_pair(kc, 0u, 0u, t0, t1); const TKey s1 = mk_key(t0, t1);   // split(kc,3)
    tf_pair(kc, 0u, 1u, t0, t1); const TKey s2 = mk_key(t0, t1);   // del uniform key
    tf_pair(kc, 0u, 2u, t0, t1); const TKey s3 = mk_key(t0, t1);

    // sub: ka, kb = split(s1); data = randint(ka) -> uses split(ka)[1]; mask = uniform(kb)
    tf_pair(s1, 0u, 0u, t0, t1); const TKey sub_a    = mk_key(t0, t1);
    tf_pair(sub_a, 0u, 1u, t0, t1); const TKey k_subdata = mk_key(t0, t1);
    tf_pair(s1, 0u, 1u, t0, t1); const TKey k_submask = mk_key(t0, t1);

    // ins: ia, ib = split(s3); flags = uniform(ia); sym = randint(ib) -> split(ib)[1]
    tf_pair(s3, 0u, 0u, t0, t1); const TKey k_insflag = mk_key(t0, t1);
    tf_pair(s3, 0u, 1u, t0, t1); const TKey ins_b    = mk_key(t0, t1);
    tf_pair(ins_b, 0u, 1u, t0, t1); const TKey k_inssym = mk_key(t0, t1);

    const float* __restrict__ xr = x + (size_t)b * L;
    float* __restrict__ orow = out + ((size_t)b * 4 + c) * Lp;

    const uint32_t base    = (uint32_t)b * (uint32_t)L;    // flat idx in (B, L)
    const uint32_t insbase = (uint32_t)b * (uint32_t)Lp;   // flat idx in (B, Lp)

    int outpos = 0;   // final write cursor
    int cur = 0;      // compacted index after deletion

    for (int l = 0; l < L; l++) {
        const uint32_t idx = base + (uint32_t)l;
        const uint32_t j   = insbase + (uint32_t)cur;
        // Three independent threefry chains -> ptxas interleaves (ILP = 3).
        // The ins-flag chain is speculative at the current compacted cursor:
        // if this element is deleted, cur is unchanged and it's recomputed
        // identically next iteration (~1% waste, removes serial dependency).
        const uint32_t bs = tf_bits(k_submask, idx);   // sub mask uniform bits
        const uint32_t bd = tf_bits(s2,       idx);    // del uniform bits
        const uint32_t bi = tf_bits(k_insflag, j);     // ins flag uniform bits
        float v = xr[l];

        if ((bs >> 9) < Ksub) {            // substitution fires (~2%): lazy data draw
            const uint32_t db = tf_bits(k_subdata, idx);   // randint lower bits % 4
            v += (float)(db & 3u);
            if (v >= 4.0f) v -= 4.0f;      // mod 4 (exact: v in [0,6])
        }

        if ((bd >> 9) >= Kdel) {           // element survives deletion
            if (outpos < Lp) orow[outpos] = v + 1.0f;
            outpos++;
            if ((bi >> 9) < Kins) {        // insertion fires (~1%): lazy symbol draw
                const uint32_t sb = tf_bits(k_inssym, j);
                if (outpos < Lp) orow[outpos] = (float)(sb & 3u) + 1.0f;
                outpos++;
            }
            cur++;
        }
    }

    // Pad tail: dropped / -1 region maps to (-1 + 1) = 0.0
    for (int j2 = outpos; j2 < Lp; j2++) orow[j2] = 0.0f;
}

extern "C" void kernel_launch(void* const* d_in, const int* in_sizes, int n_in,
                              void* d_out, int out_size) {
    const float* x = (const float*)d_in[0];   // segment_en [B, 512]
    float* out = (float*)d_out;               // [B, 4, 514] float32
    const int B = in_sizes[0] / 512;
    const int total = B * 4;
    const int block = 128;
    const int grid = (total + block - 1) / block;
    channel_m_kernel<<<grid, block>>>(x, out, B);
}

// round 3
// speedup vs baseline: 1.1574x; 1.1574x over previous
#include <cuda_runtime.h>
#include <cstdint>

// ============================================================================
// Bit-exact JAX threefry2x32 (partitionable), verified exact in R2.
// ============================================================================

#define TF_ROUND(x0, x1, r) { x0 += x1; x1 = __funnelshift_l(x1, x1, (r)); x1 ^= x0; }
#define TF_R4A(x0, x1) { TF_ROUND(x0,x1,13) TF_ROUND(x0,x1,15) TF_ROUND(x0,x1,26) TF_ROUND(x0,x1,6) }
#define TF_R4B(x0, x1) { TF_ROUND(x0,x1,17) TF_ROUND(x0,x1,29) TF_ROUND(x0,x1,16) TF_ROUND(x0,x1,24) }

struct TKey { uint32_t a, b, c; };

__device__ __forceinline__ TKey mk_key(uint32_t k0, uint32_t k1) {
    TKey k; k.a = k0; k.b = k1; k.c = k0 ^ k1 ^ 0x1BD11BDAu; return k;
}

__device__ __forceinline__ void tf_pair(const TKey k, uint32_t c0, uint32_t c1,
                                        uint32_t& o0, uint32_t& o1) {
    uint32_t x0 = c0 + k.a, x1 = c1 + k.b;
    TF_R4A(x0, x1); x0 += k.b; x1 += k.c + 1u;
    TF_R4B(x0, x1); x0 += k.c; x1 += k.a + 2u;
    TF_R4A(x0, x1); x0 += k.a; x1 += k.b + 3u;
    TF_R4B(x0, x1); x0 += k.b; x1 += k.c + 4u;
    TF_R4A(x0, x1); x0 += k.c; x1 += k.a + 5u;
    o0 = x0; o1 = x1;
}

__device__ __forceinline__ uint32_t tf_bits(const TKey k, uint32_t idx) {
    uint32_t o0, o1;
    tf_pair(k, 0u, idx, o0, o1);
    return o0 ^ o1;
}

// uniform(bits) < e  <=>  (bits >> 9) < ceil(float(e) * 2^23)   (exact)
__device__ __forceinline__ uint32_t thresh_of(float e) {
    return (uint32_t)ceil((double)e * 8388608.0);
}

// ============================================================================
// Per-channel key cache: keys depend ONLY on channel c (4 variants).
// Derived once by a tiny setup kernel; main kernel loads 15 words (L2-cached).
// Layout per channel: [submask(3), del(3), subdata(3), insflag(3), inssym(3)]
// ============================================================================

__device__ uint32_t g_keys[4][16];

__global__ void key_setup_kernel() {
    const int c = threadIdx.x;
    if (c >= 4) return;
    uint32_t t0, t1;
    const TKey root = mk_key(0u, 42u);                 // jax.random.key(42)
    tf_pair(root, 0u, (uint32_t)c, t0, t1);            // fold_in(key, c)
    const TKey kc = mk_key(t0, t1);

    tf_pair(kc, 0u, 0u, t0, t1); const TKey s1 = mk_key(t0, t1);   // split(kc,3)
    tf_pair(kc, 0u, 1u, t0, t1); const TKey s2 = mk_key(t0, t1);   // del key
    tf_pair(kc, 0u, 2u, t0, t1); const TKey s3 = mk_key(t0, t1);

    // sub: ka, kb = split(s1); data = randint(ka) -> split(ka)[1]; mask = uniform(kb)
    tf_pair(s1, 0u, 0u, t0, t1); const TKey sub_a = mk_key(t0, t1);
    tf_pair(sub_a, 0u, 1u, t0, t1); const TKey k_subdata = mk_key(t0, t1);
    tf_pair(s1, 0u, 1u, t0, t1); const TKey k_submask = mk_key(t0, t1);

    // ins: ia, ib = split(s3); flags = uniform(ia); sym = randint(ib) -> split(ib)[1]
    tf_pair(s3, 0u, 0u, t0, t1); const TKey k_insflag = mk_key(t0, t1);
    tf_pair(s3, 0u, 1u, t0, t1); const TKey ins_b = mk_key(t0, t1);
    tf_pair(ins_b, 0u, 1u, t0, t1); const TKey k_inssym = mk_key(t0, t1);

    uint32_t* kp = g_keys[c];
    kp[0] = k_submask.a; kp[1] = k_submask.b; kp[2] = k_submask.c;
    kp[3] = s2.a;        kp[4] = s2.b;        kp[5] = s2.c;
    kp[6] = k_subdata.a; kp[7] = k_subdata.b; kp[8] = k_subdata.c;
    kp[9] = k_insflag.a; kp[10] = k_insflag.b; kp[11] = k_insflag.c;
    kp[12] = k_inssym.a; kp[13] = k_inssym.b; kp[14] = k_inssym.c;
}

// ============================================================================
// Warp-per-(row, channel): lane owns 16 contiguous elements. All threefry
// chains are data-parallel; compaction via two warp scans.
// ============================================================================

#define FULLM 0xffffffffu

__global__ void __launch_bounds__(256)
channel_warp_kernel(const float* __restrict__ x, float* __restrict__ out, int B) {
    const int gw = (int)((blockIdx.x * blockDim.x + threadIdx.x) >> 5);
    const int lane = threadIdx.x & 31;
    if (gw >= B * 4) return;
    const int c = gw & 3;
    const int b = gw >> 2;

    const uint32_t Ksub = thresh_of(0.02f);
    const uint32_t Kdel = thresh_of(0.01f);
    const uint32_t Kins = thresh_of(0.01f);

    const uint32_t* kp = g_keys[c];
    const TKey kSubM = { kp[0],  kp[1],  kp[2]  };
    const TKey kDel  = { kp[3],  kp[4],  kp[5]  };
    const TKey kSubD = { kp[6],  kp[7],  kp[8]  };
    const TKey kInsF = { kp[9],  kp[10], kp[11] };
    const TKey kInsS = { kp[12], kp[13], kp[14] };

    // ---- load my 16 elements (float4 x4, fully register-resident)
    float v[16];
    const float4* __restrict__ xr4 =
        (const float4*)(x + (size_t)b * 512 + (size_t)lane * 16);
    #pragma unroll
    for (int q = 0; q < 4; q++) {
        const float4 f = xr4[q];
        v[q * 4 + 0] = f.x; v[q * 4 + 1] = f.y;
        v[q * 4 + 2] = f.z; v[q * 4 + 3] = f.w;
    }

    // ---- phase 1: sub (lazy data draw) + del keep flags. 32 independent
    // threefry chains per lane, fully unrolled -> high ILP.
    const uint32_t base = (uint32_t)b * 512u + (uint32_t)lane * 16u;
    uint32_t keepmask = 0u;
    #pragma unroll
    for (int i = 0; i < 16; i++) {
        const uint32_t idx = base + (uint32_t)i;
        const uint32_t bs = tf_bits(kSubM, idx);
        const uint32_t bd = tf_bits(kDel,  idx);
        if ((bs >> 9) < Ksub) {              // ~2%: lazy data draw
            const uint32_t db = tf_bits(kSubD, idx);
            v[i] += (float)(db & 3u);
            if (v[i] >= 4.0f) v[i] -= 4.0f;  // exact mod 4 (v in [0,6])
        }
        if ((bd >> 9) >= Kdel) keepmask |= (1u << i);
    }

    // ---- scan 1: exclusive scan of keep counts -> my compacted offset
    const int kn = __popc(keepmask);
    int incl = kn;
    #pragma unroll
    for (int d = 1; d < 32; d <<= 1) {
        const int nv = __shfl_up_sync(FULLM, incl, d);
        if (lane >= d) incl += nv;
    }
    const int ofs = incl - kn;

    // ---- phase 2: ins flags at compacted indices (parallel; computed
    // unconditionally, masked by keepmask afterwards)
    const uint32_t insbase = (uint32_t)b * 514u;
    uint32_t insmask = 0u;
    #pragma unroll
    for (int i = 0; i < 16; i++) {
        const uint32_t j = insbase +
            (uint32_t)(ofs + __popc(keepmask & ((1u << i) - 1u)));
        const uint32_t bi = tf_bits(kInsF, j);
        if ((bi >> 9) < Kins) insmask |= (1u << i);
    }
    insmask &= keepmask;

    // ---- scan 2: exclusive scan of output counts -> my output offset
    const int myout = kn + __popc(insmask);
    int incl2 = myout;
    #pragma unroll
    for (int d = 1; d < 32; d <<= 1) {
        const int nv = __shfl_up_sync(FULLM, incl2, d);
        if (lane >= d) incl2 += nv;
    }
    const int outofs = incl2 - myout;
    const int total_out = __shfl_sync(FULLM, incl2, 31);

    // ---- write phase: each lane emits its kept elems (+lazy ins symbols)
    float* __restrict__ orow = out + ((size_t)b * 4 + (size_t)c) * 514;
    int pos = outofs;
    #pragma unroll
    for (int i = 0; i < 16; i++) {
        if ((keepmask >> i) & 1u) {
            if (pos < 514) orow[pos] = v[i] + 1.0f;
            pos++;
            if ((insmask >> i) & 1u) {       // ~1%: lazy symbol draw
                const uint32_t j = insbase +
                    (uint32_t)(ofs + __popc(keepmask & ((1u << i) - 1u)));
                const uint32_t sb = tf_bits(kInsS, j);
                if (pos < 514) orow[pos] = (float)(sb & 3u) + 1.0f;
                pos++;
            }
        }
    }

    // ---- tail: pad with 0.0 (= -1 + 1)
    for (int p = total_out + lane; p < 514; p += 32) orow[p] = 0.0f;
}

extern "C" void kernel_launch(void* const* d_in, const int* in_sizes, int n_in,
                              void* d_out, int out_size) {
    const float* x = (const float*)d_in[0];   // segment_en [B, 512]
    float* out = (float*)d_out;               // [B, 4, 514] float32
    const int B = in_sizes[0] / 512;

    key_setup_kernel<<<1, 4>>>();

    const long long total_threads = (long long)B * 4 * 32;
    const int block = 256;
    const int grid = (int)((total_threads + block - 1) / block);
    channel_warp_kernel<<<grid, block>>>(x, out, B);
}

// round 4
// speedup vs baseline: 1.5149x; 1.3089x over previous
#include <cuda_runtime.h>
#include <cstdint>

// ============================================================================
// Bit-exact JAX threefry2x32 (partitionable) — verified rel_err = 0.0 in R2/R3.
// ============================================================================

#define FULLM 0xffffffffu

struct TKey { uint32_t a, b, c; };

__device__ __forceinline__ TKey mk_key(uint32_t k0, uint32_t k1) {
    TKey k; k.a = k0; k.b = k1; k.c = k0 ^ k1 ^ 0x1BD11BDAu; return k;
}

// ---- plain threefry (setup kernel only)
#define TF_ROUND(x0, x1, r) { x0 += x1; x1 = __funnelshift_l(x1, x1, (r)); x1 ^= x0; }
#define TF_R4A(x0, x1) { TF_ROUND(x0,x1,13) TF_ROUND(x0,x1,15) TF_ROUND(x0,x1,26) TF_ROUND(x0,x1,6) }
#define TF_R4B(x0, x1) { TF_ROUND(x0,x1,17) TF_ROUND(x0,x1,29) TF_ROUND(x0,x1,16) TF_ROUND(x0,x1,24) }

__device__ __forceinline__ void tf_pair(const TKey k, uint32_t c0, uint32_t c1,
                                        uint32_t& o0, uint32_t& o1) {
    uint32_t x0 = c0 + k.a, x1 = c1 + k.b;
    TF_R4A(x0, x1); x0 += k.b; x1 += k.c + 1u;
    TF_R4B(x0, x1); x0 += k.c; x1 += k.a + 2u;
    TF_R4A(x0, x1); x0 += k.a; x1 += k.b + 3u;
    TF_R4B(x0, x1); x0 += k.b; x1 += k.c + 4u;
    TF_R4A(x0, x1); x0 += k.c; x1 += k.a + 5u;
    o0 = x0; o1 = x1;
}

// ---- hot-path threefry: round-adds forced onto the IMAD/fma pipe.
// `one` is an opaque runtime value == 1 so ptxas cannot strength-reduce
// mad.lo back to IADD3; this moves 20 of ~30 adds per threefry off the
// saturated alu pipe (SHF/LOP3 are alu-locked).
__device__ __forceinline__ uint32_t addf(uint32_t a, uint32_t b, uint32_t one) {
    uint32_t d;
    asm("mad.lo.u32 %0, %1, %2, %3;" : "=r"(d) : "r"(a), "r"(one), "r"(b));
    return d;
}

#define TFF_ROUND(x0, x1, r) { x0 = addf(x0, x1, one); x1 = __funnelshift_l(x1, x1, (r)); x1 ^= x0; }
#define TFF_R4A(x0, x1) { TFF_ROUND(x0,x1,13) TFF_ROUND(x0,x1,15) TFF_ROUND(x0,x1,26) TFF_ROUND(x0,x1,6) }
#define TFF_R4B(x0, x1) { TFF_ROUND(x0,x1,17) TFF_ROUND(x0,x1,29) TFF_ROUND(x0,x1,16) TFF_ROUND(x0,x1,24) }

__device__ __forceinline__ uint32_t tff_bits(const TKey k, uint32_t idx, uint32_t one) {
    uint32_t x0 = k.a, x1 = idx + k.b;        // c0 = 0 folded
    TFF_R4A(x0, x1); x0 += k.b; x1 += k.c + 1u;
    TFF_R4B(x0, x1); x0 += k.c; x1 += k.a + 2u;
    TFF_R4A(x0, x1); x0 += k.a; x1 += k.b + 3u;
    TFF_R4B(x0, x1); x0 += k.b; x1 += k.c + 4u;
    TFF_R4A(x0, x1); x0 += k.c; x1 += k.a + 5u;
    return x0 ^ x1;
}

// uniform(bits) < e  <=>  (bits >> 9) < ceil(float(e) * 2^23)  (verified exact)
__device__ __forceinline__ uint32_t thresh_of(float e) {
    return (uint32_t)ceil((double)e * 8388608.0);
}

// ============================================================================
// Per-channel key cache (keys depend only on channel c).
// ============================================================================

__device__ uint32_t g_keys[4][16];

__global__ void key_setup_kernel() {
    const int c = threadIdx.x;
    if (c >= 4) return;
    uint32_t t0, t1;
    const TKey root = mk_key(0u, 42u);
    tf_pair(root, 0u, (uint32_t)c, t0, t1);
    const TKey kc = mk_key(t0, t1);

    tf_pair(kc, 0u, 0u, t0, t1); const TKey s1 = mk_key(t0, t1);
    tf_pair(kc, 0u, 1u, t0, t1); const TKey s2 = mk_key(t0, t1);
    tf_pair(kc, 0u, 2u, t0, t1); const TKey s3 = mk_key(t0, t1);

    tf_pair(s1, 0u, 0u, t0, t1); const TKey sub_a = mk_key(t0, t1);
    tf_pair(sub_a, 0u, 1u, t0, t1); const TKey k_subdata = mk_key(t0, t1);
    tf_pair(s1, 0u, 1u, t0, t1); const TKey k_submask = mk_key(t0, t1);

    tf_pair(s3, 0u, 0u, t0, t1); const TKey k_insflag = mk_key(t0, t1);
    tf_pair(s3, 0u, 1u, t0, t1); const TKey ins_b = mk_key(t0, t1);
    tf_pair(ins_b, 0u, 1u, t0, t1); const TKey k_inssym = mk_key(t0, t1);

    uint32_t* kp = g_keys[c];
    kp[0] = k_submask.a; kp[1] = k_submask.b; kp[2] = k_submask.c;
    kp[3] = s2.a;        kp[4] = s2.b;        kp[5] = s2.c;
    kp[6] = k_subdata.a; kp[7] = k_subdata.b; kp[8] = k_subdata.c;
    kp[9] = k_insflag.a; kp[10] = k_insflag.b; kp[11] = k_insflag.c;
    kp[12] = k_inssym.a; kp[13] = k_inssym.b; kp[14] = k_inssym.c;
}

// ============================================================================
// Warp-per-(row, channel); lane owns 16 contiguous elements.
// Rare draws deferred to per-lane bit-loops; write phase branch-free.
// ============================================================================

__global__ void __launch_bounds__(256)
channel_warp_kernel(const float* __restrict__ x, float* __restrict__ out, int B) {
    const int gw = (int)((blockIdx.x * blockDim.x + threadIdx.x) >> 5);
    const int lane = threadIdx.x & 31;
    if (gw >= B * 4) return;
    const int c = gw & 3;
    const int b = gw >> 2;

    const uint32_t Ksub = thresh_of(0.02f);
    const uint32_t Kdel = thresh_of(0.01f);
    const uint32_t Kins = thresh_of(0.01f);

    const uint32_t* kp = g_keys[c];
    const uint32_t one = (kp[0] >> 31) | 1u;      // opaque runtime 1
    const TKey kSubM = { kp[0],  kp[1],  kp[2]  };
    const TKey kDel  = { kp[3],  kp[4],  kp[5]  };

    // ---- load my 16 elements
    float v[16];
    const float4* __restrict__ xr4 =
        (const float4*)(x + (size_t)b * 512 + (size_t)lane * 16);
    #pragma unroll
    for (int q = 0; q < 4; q++) {
        const float4 f = xr4[q];
        v[q * 4 + 0] = f.x; v[q * 4 + 1] = f.y;
        v[q * 4 + 2] = f.z; v[q * 4 + 3] = f.w;
    }

    // ---- phase 1: sub-need + keep flags only (no rare bodies in this loop)
    const uint32_t base = (uint32_t)b * 512u + (uint32_t)lane * 16u;
    uint32_t keepmask = 0u, subneed = 0u;
    #pragma unroll
    for (int i = 0; i < 16; i++) {
        const uint32_t idx = base + (uint32_t)i;
        const uint32_t bs = tff_bits(kSubM, idx, one);
        const uint32_t bd = tff_bits(kDel,  idx, one);
        if ((bs >> 9) < Ksub)  subneed  |= (1u << i);
        if ((bd >> 9) >= Kdel) keepmask |= (1u << i);
    }

    // ---- deferred sub draws: per-lane bit loop, 2-bit deltas packed in a word
    uint32_t subdelta = 0u;
    {
        const TKey kSubD = { kp[6], kp[7], kp[8] };
        uint32_t m = subneed;
        while (m) {
            const int i = __ffs(m) - 1; m &= m - 1u;
            const uint32_t db = tff_bits(kSubD, base + (uint32_t)i, one);
            subdelta |= (db & 3u) << (2 * i);
        }
    }

    // ---- scan 1: exclusive scan of keep counts -> compacted offset
    const int kn = __popc(keepmask);
    int incl = kn;
    #pragma unroll
    for (int d = 1; d < 32; d <<= 1) {
        const int nv = __shfl_up_sync(FULLM, incl, d);
        if (lane >= d) incl += nv;
    }
    const int ofs = incl - kn;

    // ---- phase 2: ins flags at compacted indices (unconditional, masked after)
    const uint32_t insbase = (uint32_t)b * 514u;
    uint32_t insmask = 0u;
    #pragma unroll
    for (int i = 0; i < 16; i++) {
        const uint32_t j = insbase +
            (uint32_t)(ofs + __popc(keepmask & ((1u << i) - 1u)));
        const TKey kInsF = { kp[9], kp[10], kp[11] };
        const uint32_t bi = tff_bits(kInsF, j, one);
        if ((bi >> 9) < Kins) insmask |= (1u << i);
    }
    insmask &= keepmask;

    // ---- scan 2: output offsets
    const int myout = kn + __popc(insmask);
    int incl2 = myout;
    #pragma unroll
    for (int d = 1; d < 32; d <<= 1) {
        const int nv = __shfl_up_sync(FULLM, incl2, d);
        if (lane >= d) incl2 += nv;
    }
    const int outofs = incl2 - myout;
    const int total_out = __shfl_sync(FULLM, incl2, 31);

    float* __restrict__ orow = out + ((size_t)b * 4 + (size_t)c) * 514;

    // ---- write kept elements: branch-free, popc positions, predicated STG
    #pragma unroll
    for (int i = 0; i < 16; i++) {
        const uint32_t below = (1u << i) - 1u;
        const int pos = outofs + __popc(keepmask & below) + __popc(insmask & below);
        float vv = v[i] + (float)((subdelta >> (2 * i)) & 3u);  // +0.0 exact when no sub
        if (vv >= 4.0f) vv -= 4.0f;                              // exact mod 4
        if (((keepmask >> i) & 1u) && pos < 514) orow[pos] = vv + 1.0f;
    }

    // ---- inserted symbols: rare per-lane bit loop
    {
        const TKey kInsS = { kp[12], kp[13], kp[14] };
        uint32_t m = insmask;
        while (m) {
            const int i = __ffs(m) - 1; m &= m - 1u;
            const uint32_t below = (1u << i) - 1u;
            const int nk = __popc(keepmask & below);
            const uint32_t j = insbase + (uint32_t)(ofs + nk);
            const int pos = outofs + nk + __popc(insmask & below) + 1;  // slot after kept elem i
            const uint32_t sb = tff_bits(kInsS, j, one);
            if (pos < 514) orow[pos] = (float)(sb & 3u) + 1.0f;
        }
    }

    // ---- tail padding: 0.0 (= -1 + 1)
    for (int p = total_out + lane; p < 514; p += 32) orow[p] = 0.0f;
}

extern "C" void kernel_launch(void* const* d_in, const int* in_sizes, int n_in,
                              void* d_out, int out_size) {
    const float* x = (const float*)d_in[0];   // segment_en [B, 512]
    float* out = (float*)d_out;               // [B, 4, 514] float32
    const int B = in_sizes[0] / 512;

    key_setup_kernel<<<1, 4>>>();

    const long long total_threads = (long long)B * 4 * 32;
    const int block = 256;
    const int grid = (int)((total_threads + block - 1) / block);
    channel_warp_kernel<<<grid, block>>>(x, out, B);
}

// round 5
// speedup vs baseline: 1.5536x; 1.0256x over previous
#include <cuda_runtime.h>
#include <cstdint>

// ============================================================================
// Bit-exact JAX threefry2x32 (partitionable) — rel_err = 0.0 verified R2-R4.
// R5: every add forced onto the IMAD/fma pipe (alu pipe = 93% saturated in R4);
//     threshold compares pre-shifted to kill one SHF per draw.
// ============================================================================

#define FULLM 0xffffffffu

struct TKey { uint32_t a, b, c; };

__device__ __forceinline__ TKey mk_key(uint32_t k0, uint32_t k1) {
    TKey k; k.a = k0; k.b = k1; k.c = k0 ^ k1 ^ 0x1BD11BDAu; return k;
}

// ---- plain threefry (setup kernel only)
#define TF_ROUND(x0, x1, r) { x0 += x1; x1 = __funnelshift_l(x1, x1, (r)); x1 ^= x0; }
#define TF_R4A(x0, x1) { TF_ROUND(x0,x1,13) TF_ROUND(x0,x1,15) TF_ROUND(x0,x1,26) TF_ROUND(x0,x1,6) }
#define TF_R4B(x0, x1) { TF_ROUND(x0,x1,17) TF_ROUND(x0,x1,29) TF_ROUND(x0,x1,16) TF_ROUND(x0,x1,24) }

__device__ __forceinline__ void tf_pair(const TKey k, uint32_t c0, uint32_t c1,
                                        uint32_t& o0, uint32_t& o1) {
    uint32_t x0 = c0 + k.a, x1 = c1 + k.b;
    TF_R4A(x0, x1); x0 += k.b; x1 += k.c + 1u;
    TF_R4B(x0, x1); x0 += k.c; x1 += k.a + 2u;
    TF_R4A(x0, x1); x0 += k.a; x1 += k.b + 3u;
    TF_R4B(x0, x1); x0 += k.b; x1 += k.c + 4u;
    TF_R4A(x0, x1); x0 += k.c; x1 += k.a + 5u;
    o0 = x0; o1 = x1;
}

// ---- hot-path add on the IMAD/fma pipe. `one` is an opaque runtime 1 so
// ptxas cannot strength-reduce mad.lo back to IADD3 (alu pipe).
__device__ __forceinline__ uint32_t addf(uint32_t a, uint32_t b, uint32_t one) {
    uint32_t d;
    asm("mad.lo.u32 %0, %1, %2, %3;" : "=r"(d) : "r"(a), "r"(one), "r"(b));
    return d;
}

// Expanded key schedule: all injection constants precomputed (warp-uniform).
struct TSched {
    uint32_t a, b, c;      // base key words
    uint32_t c1, a2, b3, c4, a5;   // k.c+1, k.a+2, k.b+3, k.c+4, k.a+5
};

__device__ __forceinline__ TSched mk_sched(uint32_t a, uint32_t b, uint32_t c) {
    TSched s; s.a = a; s.b = b; s.c = c;
    s.c1 = c + 1u; s.a2 = a + 2u; s.b3 = b + 3u; s.c4 = c + 4u; s.a5 = a + 5u;
    return s;
}

#define TFF_ROUND(x0, x1, r) { x0 = addf(x0, x1, one); x1 = __funnelshift_l(x1, x1, (r)); x1 ^= x0; }
#define TFF_R4A(x0, x1) { TFF_ROUND(x0,x1,13) TFF_ROUND(x0,x1,15) TFF_ROUND(x0,x1,26) TFF_ROUND(x0,x1,6) }
#define TFF_R4B(x0, x1) { TFF_ROUND(x0,x1,17) TFF_ROUND(x0,x1,29) TFF_ROUND(x0,x1,16) TFF_ROUND(x0,x1,24) }

// threefry2x32 at counter (0, idx), all adds on fma pipe:
//   alu ops: 20 SHF + 21 LOP3 ; fma ops: 31 IMAD
__device__ __forceinline__ uint32_t tff_bits(const TSched k, uint32_t idx, uint32_t one) {
    uint32_t x0 = k.a, x1 = addf(idx, k.b, one);
    TFF_R4A(x0, x1); x0 = addf(x0, k.b, one); x1 = addf(x1, k.c1, one);
    TFF_R4B(x0, x1); x0 = addf(x0, k.c, one); x1 = addf(x1, k.a2, one);
    TFF_R4A(x0, x1); x0 = addf(x0, k.a, one); x1 = addf(x1, k.b3, one);
    TFF_R4B(x0, x1); x0 = addf(x0, k.b, one); x1 = addf(x1, k.c4, one);
    TFF_R4A(x0, x1); x0 = addf(x0, k.c, one); x1 = addf(x1, k.a5, one);
    return x0 ^ x1;
}

// Pre-shifted threshold: uniform(bits) < e  <=>  bits < (ceil(e*2^23) << 9).
// Exact for unsigned since the RHS has zero low bits (K*512, K < 2^23).
__device__ __forceinline__ uint32_t thresh_shifted(float e) {
    return ((uint32_t)ceil((double)e * 8388608.0)) << 9;
}

// ============================================================================
// Per-channel key cache (keys depend only on channel c).
// ============================================================================

__device__ uint32_t g_keys[4][16];

__global__ void key_setup_kernel() {
    const int c = threadIdx.x;
    if (c >= 4) return;
    uint32_t t0, t1;
    const TKey root = mk_key(0u, 42u);
    tf_pair(root, 0u, (uint32_t)c, t0, t1);
    const TKey kc = mk_key(t0, t1);

    tf_pair(kc, 0u, 0u, t0, t1); const TKey s1 = mk_key(t0, t1);
    tf_pair(kc, 0u, 1u, t0, t1); const TKey s2 = mk_key(t0, t1);
    tf_pair(kc, 0u, 2u, t0, t1); const TKey s3 = mk_key(t0, t1);

    tf_pair(s1, 0u, 0u, t0, t1); const TKey sub_a = mk_key(t0, t1);
    tf_pair(sub_a, 0u, 1u, t0, t1); const TKey k_subdata = mk_key(t0, t1);
    tf_pair(s1, 0u, 1u, t0, t1); const TKey k_submask = mk_key(t0, t1);

    tf_pair(s3, 0u, 0u, t0, t1); const TKey k_insflag = mk_key(t0, t1);
    tf_pair(s3, 0u, 1u, t0, t1); const TKey ins_b = mk_key(t0, t1);
    tf_pair(ins_b, 0u, 1u, t0, t1); const TKey k_inssym = mk_key(t0, t1);

    uint32_t* kp = g_keys[c];
    kp[0] = k_submask.a; kp[1] = k_submask.b; kp[2] = k_submask.c;
    kp[3] = s2.a;        kp[4] = s2.b;        kp[5] = s2.c;
    kp[6] = k_subdata.a; kp[7] = k_subdata.b; kp[8] = k_subdata.c;
    kp[9] = k_insflag.a; kp[10] = k_insflag.b; kp[11] = k_insflag.c;
    kp[12] = k_inssym.a; kp[13] = k_inssym.b; kp[14] = k_inssym.c;
}

// ============================================================================
// Warp-per-(row, channel); lane owns 16 contiguous elements.
// ============================================================================

__global__ void __launch_bounds__(256)
channel_warp_kernel(const float* __restrict__ x, float* __restrict__ out, int B) {
    const int gw = (int)((blockIdx.x * blockDim.x + threadIdx.x) >> 5);
    const int lane = threadIdx.x & 31;
    if (gw >= B * 4) return;
    const int c = gw & 3;
    const int b = gw >> 2;

    const uint32_t KsubS = thresh_shifted(0.02f);
    const uint32_t KdelS = thresh_shifted(0.01f);
    const uint32_t KinsS = thresh_shifted(0.01f);

    const uint32_t* kp = g_keys[c];
    const uint32_t one = (kp[0] >> 31) | 1u;      // opaque runtime 1
    const TSched kSubM = mk_sched(kp[0], kp[1], kp[2]);
    const TSched kDel  = mk_sched(kp[3], kp[4], kp[5]);

    // ---- load my 16 elements
    float v[16];
    const float4* __restrict__ xr4 =
        (const float4*)(x + (size_t)b * 512 + (size_t)lane * 16);
    #pragma unroll
    for (int q = 0; q < 4; q++) {
        const float4 f = xr4[q];
        v[q * 4 + 0] = f.x; v[q * 4 + 1] = f.y;
        v[q * 4 + 2] = f.z; v[q * 4 + 3] = f.w;
    }

    // ---- phase 1: sub-need + keep flags (rare bodies deferred)
    const uint32_t base = (uint32_t)b * 512u + (uint32_t)lane * 16u;
    uint32_t keepmask = 0u, subneed = 0u;
    #pragma unroll
    for (int i = 0; i < 16; i++) {
        const uint32_t idx = base + (uint32_t)i;
        const uint32_t bs = tff_bits(kSubM, idx, one);
        const uint32_t bd = tff_bits(kDel,  idx, one);
        if (bs < KsubS)  subneed  |= (1u << i);
        if (bd >= KdelS) keepmask |= (1u << i);
    }

    // ---- deferred sub draws: per-lane bit loop, 2-bit packed deltas
    uint32_t subdelta = 0u;
    {
        const TSched kSubD = mk_sched(kp[6], kp[7], kp[8]);
        uint32_t m = subneed;
        while (m) {
            const int i = __ffs(m) - 1; m &= m - 1u;
            const uint32_t db = tff_bits(kSubD, base + (uint32_t)i, one);
            subdelta |= (db & 3u) << (2 * i);
        }
    }

    // ---- scan 1: exclusive scan of keep counts -> compacted offset
    const int kn = __popc(keepmask);
    int incl = kn;
    #pragma unroll
    for (int d = 1; d < 32; d <<= 1) {
        const int nv = __shfl_up_sync(FULLM, incl, d);
        if (lane >= d) incl += nv;
    }
    const int ofs = incl - kn;

    // ---- phase 2: ins flags at compacted indices (unconditional, masked after)
    const uint32_t insbase = (uint32_t)b * 514u;
    uint32_t insmask = 0u;
    {
        const TSched kInsF = mk_sched(kp[9], kp[10], kp[11]);
        #pragma unroll
        for (int i = 0; i < 16; i++) {
            const uint32_t j = insbase +
                (uint32_t)(ofs + __popc(keepmask & ((1u << i) - 1u)));
            const uint32_t bi = tff_bits(kInsF, j, one);
            if (bi < KinsS) insmask |= (1u << i);
        }
    }
    insmask &= keepmask;

    // ---- scan 2: output offsets
    const int myout = kn + __popc(insmask);
    int incl2 = myout;
    #pragma unroll
    for (int d = 1; d < 32; d <<= 1) {
        const int nv = __shfl_up_sync(FULLM, incl2, d);
        if (lane >= d) incl2 += nv;
    }
    const int outofs = incl2 - myout;
    const int total_out = __shfl_sync(FULLM, incl2, 31);

    float* __restrict__ orow = out + ((size_t)b * 4 + (size_t)c) * 514;

    // ---- write kept elements: branch-free, popc positions, predicated STG
    #pragma unroll
    for (int i = 0; i < 16; i++) {
        const uint32_t below = (1u << i) - 1u;
        const int pos = outofs + __popc(keepmask & below) + __popc(insmask & below);
        float vv = v[i] + (float)((subdelta >> (2 * i)) & 3u);  // +0.0 exact when no sub
        if (vv >= 4.0f) vv -= 4.0f;                              // exact mod 4
        if (((keepmask >> i) & 1u) && pos < 514) orow[pos] = vv + 1.0f;
    }

    // ---- inserted symbols: rare per-lane bit loop
    {
        const TSched kInsS2 = mk_sched(kp[12], kp[13], kp[14]);
        uint32_t m = insmask;
        while (m) {
            const int i = __ffs(m) - 1; m &= m - 1u;
            const uint32_t below = (1u << i) - 1u;
            const int nk = __popc(keepmask & below);
            const uint32_t j = insbase + (uint32_t)(ofs + nk);
            const int pos = outofs + nk + __popc(insmask & below) + 1;
            const uint32_t sb = tff_bits(kInsS2, j, one);
            if (pos < 514) orow[pos] = (float)(sb & 3u) + 1.0f;
        }
    }

    // ---- tail padding: 0.0 (= -1 + 1)
    for (int p = total_out + lane; p < 514; p += 32) orow[p] = 0.0f;
}

extern "C" void kernel_launch(void* const* d_in, const int* in_sizes, int n_in,
                              void* d_out, int out_size) {
    const float* x = (const float*)d_in[0];   // segment_en [B, 512]
    float* out = (float*)d_out;               // [B, 4, 514] float32
    const int B = in_sizes[0] / 512;

    key_setup_kernel<<<1, 4>>>();

    const long long total_threads = (long long)B * 4 * 32;
    const int block = 256;
    const int grid = (int)((total_threads + block - 1) / block);
    channel_warp_kernel<<<grid, block>>>(x, out, B);
}